// round 14
// baseline (speedup 1.0000x reference)
#include <cuda_runtime.h>
#include <cuda_fp16.h>
#include <math.h>

#define N_NODES 100000
#define N_EDGES 3200000
#define N_GRAPHS 64
#define SCAN_BLOCKS 391            // ceil(100000/256)

typedef unsigned long long ull;
#define C16 (1.f / 65535.f)

// ---------------- scratch -----------------------------------------------------
__device__ __align__(16) uint2 g_es[N_EDGES + 8];    // sorted by dst: {src, p1q<<16|p0q}
__device__ int   g_deg[N_NODES];     // zeroed by k_agg2 after last use (invariant)
__device__ int   g_offs[N_NODES];    // exclusive offsets; scatter bumps to offs+deg
__device__ ull   g_stat[SCAN_BLOCKS];// lookback: (1<<32)|aggregate
__device__ __align__(4) __half g_h1[N_NODES * 16];   // raw h1 (pre-BN), fp16
__device__ float g_stats1[32];          // sum[16], sumsq[16]
__device__ float g_stats2[64];          // sum[32], sumsq[32]
__device__ __align__(16) float g_gsum[N_GRAPHS * 32];
__device__ float g_gcnt[N_GRAPHS];
__device__ int   g_i64;

__device__ __forceinline__ float elu1(float v) { return v > 0.f ? v : expm1f(v); }

__device__ __forceinline__ int load_idx(const void* p, long long i, int f64) {
    return f64 ? (int)((const long long*)p)[i] : ((const int*)p)[i];
}

// per-warp int64-vs-int32 detection from edge_index words (warp-uniform result)
__device__ __forceinline__ int detect_i64(const int* ei, int lane) {
    int w = ei[2 * lane + 1];
    return __all_sync(0xffffffffu, w == 0) ? 1 : 0;
}

// ---------------- f32x2 packed helpers ----------------------------------------
__device__ __forceinline__ ull pkf(float lo, float hi) {
    ull r; asm("mov.b64 %0, {%1, %2};" : "=l"(r) : "f"(lo), "f"(hi)); return r;
}
__device__ __forceinline__ float2 unpk(ull v) {
    float2 f; asm("mov.b64 {%0, %1}, %2;" : "=f"(f.x), "=f"(f.y) : "l"(v)); return f;
}
__device__ __forceinline__ ull fma2(ull a, ull b, ull c) {
    ull d; asm("fma.rn.f32x2 %0, %1, %2, %3;" : "=l"(d) : "l"(a), "l"(b), "l"(c)); return d;
}
__device__ __forceinline__ ull add2(ull a, ull b) {
    ull d; asm("add.rn.f32x2 %0, %1, %2;" : "=l"(d) : "l"(a), "l"(b)); return d;
}
__device__ __forceinline__ ull sx2(ull v, int m) {
    unsigned lo = (unsigned)v, hi = (unsigned)(v >> 32);
    lo = __shfl_xor_sync(0xffffffffu, lo, m);
    hi = __shfl_xor_sync(0xffffffffu, hi, m);
    ull o; asm("mov.b64 %0, {%1, %2};" : "=l"(o) : "r"(lo), "r"(hi)); return o;
}

// ---------------- count (4 edges/thread) + detect/zero folded into block 0 -----
__global__ __launch_bounds__(256) void k_count(const void* __restrict__ ei) {
    int t = threadIdx.x, lane = t & 31;
    int f64 = detect_i64((const int*)ei, lane);
    if (blockIdx.x == 0) {
        for (int i = t; i < SCAN_BLOCKS; i += 256) g_stat[i] = 0ull;
        for (int i = t; i < N_GRAPHS * 32; i += 256) g_gsum[i] = 0.f;
        if (t < 32) g_stats1[t] = 0.f;
        if (t < 64) g_stats2[t] = 0.f;
        if (t < N_GRAPHS) g_gcnt[t] = 0.f;
        if (t == 0) g_i64 = f64;
    }
    long long base = (long long)(blockIdx.x * 256 + t) * 4;
    if (base >= N_EDGES) return;
    int d0, d1, d2, d3;
    if (f64) {
        const longlong2* p = (const longlong2*)((const long long*)ei + N_EDGES + base);
        longlong2 a = p[0], b = p[1];
        d0 = (int)a.x; d1 = (int)a.y; d2 = (int)b.x; d3 = (int)b.y;
    } else {
        int4 v = *(const int4*)((const int*)ei + N_EDGES + base);
        d0 = v.x; d1 = v.y; d2 = v.z; d3 = v.w;
    }
    atomicAdd(&g_deg[d0], 1);
    atomicAdd(&g_deg[d1], 1);
    atomicAdd(&g_deg[d2], 1);
    atomicAdd(&g_deg[d3], 1);
}

// ---------------- single-pass exclusive scan (decoupled lookback) --------------
__global__ __launch_bounds__(256) void k_scan() {
    int t = threadIdx.x, lane = t & 31, warp = t >> 5;
    int b = blockIdx.x;
    int i = b * 256 + t;
    int deg = (i < N_NODES) ? g_deg[i] : 0;
    int v = deg, orig = deg;
#pragma unroll
    for (int d = 1; d < 32; d <<= 1) {
        int u = __shfl_up_sync(0xffffffffu, v, d);
        if (lane >= d) v += u;
    }
    __shared__ int sW[8];
    __shared__ int sPrefix;
    if (lane == 31) sW[warp] = v;
    __syncthreads();
    if (t < 8) {
        int xv = sW[t], ox = xv;
#pragma unroll
        for (int d = 1; d < 8; d <<= 1) {
            int u = __shfl_up_sync(0xffu, xv, d);
            if (t >= d) xv += u;
        }
        sW[t] = xv - ox;
    }
    __syncthreads();
    int excl = v - orig + sW[warp];
    if (t == 255)
        *(volatile ull*)&g_stat[b] = (1ull << 32) | (unsigned)(excl + deg);
    if (warp == 0) {
        int sum = 0;
        for (int bj = b - 1 - lane; ; bj -= 32) {
            if (__all_sync(0xffffffffu, bj < 0)) break;
            if (bj >= 0) {
                ull vv;
                do { vv = *(volatile ull*)&g_stat[bj]; } while ((unsigned)(vv >> 32) == 0u);
                sum += (int)(unsigned)vv;
            }
        }
#pragma unroll
        for (int s = 16; s > 0; s >>= 1) sum += __shfl_xor_sync(0xffffffffu, sum, s);
        if (lane == 0) sPrefix = sum;
    }
    __syncthreads();
    if (i < N_NODES)
        g_offs[i] = sPrefix + excl;
}

// ---------------- scatter: 4 edges per thread, atomics on g_offs ---------------
__global__ __launch_bounds__(256) void k_scatter(const void* __restrict__ ei,
                                                 const float* __restrict__ ea) {
    int lane = threadIdx.x & 31;
    int f64 = detect_i64((const int*)ei, lane);
    long long base = (long long)(blockIdx.x * 256 + threadIdx.x) * 4;
    if (base >= N_EDGES) return;
    int s0, s1, s2, s3, d0, d1, d2, d3;
    if (f64) {
        const longlong2* ps = (const longlong2*)((const long long*)ei + base);
        longlong2 a = ps[0], b = ps[1];
        s0 = (int)a.x; s1 = (int)a.y; s2 = (int)b.x; s3 = (int)b.y;
        const longlong2* pd = (const longlong2*)((const long long*)ei + N_EDGES + base);
        longlong2 c = pd[0], d = pd[1];
        d0 = (int)c.x; d1 = (int)c.y; d2 = (int)d.x; d3 = (int)d.y;
    } else {
        int4 vs = *(const int4*)((const int*)ei + base);
        s0 = vs.x; s1 = vs.y; s2 = vs.z; s3 = vs.w;
        int4 vd = *(const int4*)((const int*)ei + N_EDGES + base);
        d0 = vd.x; d1 = vd.y; d2 = vd.z; d3 = vd.w;
    }
    float4 ea0 = *(const float4*)(ea + 2 * base);
    float4 ea1 = *(const float4*)(ea + 2 * base + 4);
    int p0 = atomicAdd(&g_offs[d0], 1);
    int p1 = atomicAdd(&g_offs[d1], 1);
    int p2 = atomicAdd(&g_offs[d2], 1);
    int p3 = atomicAdd(&g_offs[d3], 1);
    unsigned q00 = __float2uint_rn(ea0.x * 65535.f), q01 = __float2uint_rn(ea0.y * 65535.f);
    unsigned q10 = __float2uint_rn(ea0.z * 65535.f), q11 = __float2uint_rn(ea0.w * 65535.f);
    unsigned q20 = __float2uint_rn(ea1.x * 65535.f), q21 = __float2uint_rn(ea1.y * 65535.f);
    unsigned q30 = __float2uint_rn(ea1.z * 65535.f), q31 = __float2uint_rn(ea1.w * 65535.f);
    g_es[p0] = make_uint2((unsigned)s0, (q01 << 16) | q00);
    g_es[p1] = make_uint2((unsigned)s1, (q11 << 16) | q10);
    g_es[p2] = make_uint2((unsigned)s2, (q21 << 16) | q20);
    g_es[p3] = make_uint2((unsigned)s3, (q31 << 16) | q30);
}

// ---------------- layer1: gather-aggregate + conv + ELU + BN stats ------------
// NOTE: g_offs[n] holds offs+deg (post-scatter); base = g_offs[n] - deg.
__global__ __launch_bounds__(256) void k_agg1(const float* __restrict__ x,
                                              const float* __restrict__ W1) {
    __shared__ float sW[192];            // W1[k*48 + i*16 + o]
    __shared__ float sS[8][12];
    __shared__ float sH[8][16];
    int t = threadIdx.x;
    if (t < 192) sW[t] = W1[t];
    __syncthreads();
    int warp = t >> 5, lane = t & 31;
    int n = blockIdx.x * 8 + warp;
    int q = lane & 3, grp = lane >> 2;   // 8 edges per iter, 4 lanes/edge
    int deg = g_deg[n];
    int base = g_offs[n] - deg;
    float a0 = 0.f, a1 = 0.f, a2 = 0.f, a3 = 0.f;   // S[k][i=q]
    for (int eb = 0; eb < deg; eb += 8) {
        uint2 r = g_es[base + eb + grp];             // broadcast: 4 lanes same addr
        float act = ((eb + grp) < deg) ? 1.f : 0.f;
        float f0 = (float)(r.y & 0xffffu), f1 = (float)(r.y >> 16);
        float p0 = f0 * C16, p1 = f1 * C16;
        float q0 = fmaf(f0, -C16, 1.f), q1 = fmaf(f1, -C16, 1.f);
        float xv = 0.f;
        if (q < 3) xv = x[r.x * 3u + (unsigned)q];
        xv *= act;
        float q0q1 = q1 * q0;
        a0 += q0q1 * xv;
        a1 += (q1 * p0) * xv;
        a2 += (p1 * q0) * xv;
        a3 += (p1 * p0) * xv;
    }
#pragma unroll
    for (int s = 4; s < 32; s <<= 1) {
        a0 += __shfl_xor_sync(0xffffffffu, a0, s);
        a1 += __shfl_xor_sync(0xffffffffu, a1, s);
        a2 += __shfl_xor_sync(0xffffffffu, a2, s);
        a3 += __shfl_xor_sync(0xffffffffu, a3, s);
    }
    if (lane < 3) {
        sS[warp][0 + lane] = a0;
        sS[warp][3 + lane] = a1;
        sS[warp][6 + lane] = a2;
        sS[warp][9 + lane] = a3;
    }
    __syncwarp();
    if (lane < 16) {
        float s = 0.f;
#pragma unroll
        for (int k = 0; k < 4; k++)
#pragma unroll
            for (int i = 0; i < 3; i++)
                s += sS[warp][k * 3 + i] * sW[k * 48 + i * 16 + lane];
        float d = (float)max(deg, 1);
        float h = elu1(s / d);
        g_h1[(size_t)n * 16 + lane] = __float2half(h);
        sH[warp][lane] = h;
    }
    __syncthreads();
    if (t < 16) {
        float tot = 0.f, sq = 0.f;
#pragma unroll
        for (int w = 0; w < 8; w++) { float v = sH[w][t]; tot += v; sq += v * v; }
        atomicAdd(&g_stats1[t], tot);
        atomicAdd(&g_stats1[16 + t], sq);
    }
}

// ---------------- layer2: 8 lanes/edge, 4 edges/iter; conv+ELU+stats+pool ------
// Also restores g_deg[n] = 0 (last reader) so the next call needs no memset.
__global__ __launch_bounds__(256) void k_agg2(const float* __restrict__ W2,
                                              const void* __restrict__ batch,
                                              const float* __restrict__ gam1,
                                              const float* __restrict__ bet1) {
    __shared__ float sWt[32 * 68];        // transposed W2: [o][j], j = k*16+i
    __shared__ float sAB[32];             // A[16], B[16]
    __shared__ __align__(16) float sT[8][64];
    __shared__ float sH[8][32];
    __shared__ int   sGid[8];
    int t = threadIdx.x;
    for (int idx = t; idx < 2048; idx += 256) {
        int j = idx >> 5, o = idx & 31;
        sWt[o * 68 + j] = W2[idx];
    }
    if (t < 16) {
        float mu = g_stats1[t] * (1.f / N_NODES);
        float var = g_stats1[16 + t] * (1.f / N_NODES) - mu * mu;
        float A = rsqrtf(var + 1e-5f) * gam1[t];
        sAB[t] = A;
        sAB[16 + t] = bet1[t] - mu * A;
    }
    __syncthreads();
    int warp = t >> 5, lane = t & 31;
    int n = blockIdx.x * 8 + warp;
    int q = lane & 7, og = lane >> 3;    // 4 edges per iter, 8 lanes/edge
    int deg = g_deg[n];
    int base = g_offs[n] - deg;
    if (lane == 0) g_deg[n] = 0;         // restore zero-invariant for next call
    ull Sx01 = 0, Sx23 = 0, Sy01 = 0, Sy23 = 0, C01 = 0, C23 = 0;
    for (int eb = 0; eb < deg; eb += 4) {
        uint2 r = g_es[base + eb + og];              // broadcast: 8 lanes same addr
        float act = ((eb + og) < deg) ? 1.f : 0.f;
        float f0 = (float)(r.y & 0xffffu), f1 = (float)(r.y >> 16);
        float c16a = C16 * act;
        float p0a = f0 * c16a, q0a = fmaf(f0, -c16a, act);   // act folded into decode
        float p1 = f1 * C16, q1 = fmaf(f1, -C16, 1.f);
        unsigned raw = *(const unsigned*)((const char*)g_h1 + (size_t)r.x * 32 + q * 4);
        float2 hv = __half22float2(*reinterpret_cast<__half2*>(&raw));
        ull q0p0 = pkf(q0a, p0a);
        ull b01 = fma2(pkf(q1, q1), q0p0, 0ull);
        ull b23 = fma2(pkf(p1, p1), q0p0, 0ull);
        ull hx = pkf(hv.x, hv.x);
        ull hy = pkf(hv.y, hv.y);
        Sx01 = fma2(b01, hx, Sx01);
        Sx23 = fma2(b23, hx, Sx23);
        Sy01 = fma2(b01, hy, Sy01);
        Sy23 = fma2(b23, hy, Sy23);
        C01 = add2(C01, b01);
        C23 = add2(C23, b23);
    }
#pragma unroll
    for (int s = 8; s < 32; s <<= 1) {
        Sx01 = add2(Sx01, sx2(Sx01, s));
        Sx23 = add2(Sx23, sx2(Sx23, s));
        Sy01 = add2(Sy01, sx2(Sy01, s));
        Sy23 = add2(Sy23, sx2(Sy23, s));
        C01 = add2(C01, sx2(C01, s));
        C23 = add2(C23, sx2(C23, s));
    }
    if (lane < 8) {
        float2 x01 = unpk(Sx01), x23 = unpk(Sx23);
        float2 y01 = unpk(Sy01), y23 = unpk(Sy23);
        float2 c01 = unpk(C01), c23 = unpk(C23);
        int i0 = 2 * q, i1 = 2 * q + 1;
        float A0 = sAB[i0], B0 = sAB[16 + i0];
        float A1 = sAB[i1], B1 = sAB[16 + i1];
        sT[warp][0 * 16 + i0] = A0 * x01.x + B0 * c01.x;
        sT[warp][1 * 16 + i0] = A0 * x01.y + B0 * c01.y;
        sT[warp][2 * 16 + i0] = A0 * x23.x + B0 * c23.x;
        sT[warp][3 * 16 + i0] = A0 * x23.y + B0 * c23.y;
        sT[warp][0 * 16 + i1] = A1 * y01.x + B1 * c01.x;
        sT[warp][1 * 16 + i1] = A1 * y01.y + B1 * c01.y;
        sT[warp][2 * 16 + i1] = A1 * y23.x + B1 * c23.x;
        sT[warp][3 * 16 + i1] = A1 * y23.y + B1 * c23.y;
    }
    if (lane == 0) sGid[warp] = load_idx(batch, n, g_i64);
    __syncwarp();
    float s = 0.f;
    const float4* wp = (const float4*)(sWt + lane * 68);
    const float4* tp = (const float4*)(sT[warp]);
#pragma unroll
    for (int jj = 0; jj < 16; jj++) {
        float4 w4 = wp[jj], t4 = tp[jj];
        s += t4.x * w4.x + t4.y * w4.y + t4.z * w4.z + t4.w * w4.w;
    }
    float d = (float)max(deg, 1);
    float h = elu1(s / d);
    sH[warp][lane] = h;
    __syncthreads();
    if (t < 32) {
        float tot = 0.f, sq = 0.f;
#pragma unroll
        for (int w = 0; w < 8; w++) { float v = sH[w][t]; tot += v; sq += v * v; }
        atomicAdd(&g_stats2[t], tot);
        atomicAdd(&g_stats2[32 + t], sq);
        int g0 = sGid[0];
        bool uni = true;
#pragma unroll
        for (int w = 1; w < 8; w++) uni &= (sGid[w] == g0);
        if (uni) {
            atomicAdd(&g_gsum[g0 * 32 + t], tot);
            if (t == 0) atomicAdd(&g_gcnt[g0], 8.f);
        } else {
#pragma unroll
            for (int w = 0; w < 8; w++) {
                atomicAdd(&g_gsum[sGid[w] * 32 + t], sH[w][t]);
                if (t == 0) atomicAdd(&g_gcnt[sGid[w]], 1.f);
            }
        }
    }
}

// ---------------- final: bn2 params + bn2(mean-pool) @ fc^T --------------------
__global__ __launch_bounds__(640) void k_final(const float* __restrict__ gam,
                                               const float* __restrict__ bet,
                                               const float* __restrict__ fc,
                                               float* __restrict__ out) {
    __shared__ float bn[64];
    int t = threadIdx.x;
    if (t < 32) {
        float mu = g_stats2[t] * (1.f / N_NODES);
        float var = g_stats2[32 + t] * (1.f / N_NODES) - mu * mu;
        float A = rsqrtf(var + 1e-5f) * gam[t];
        bn[t] = A;
        bn[32 + t] = bet[t] - mu * A;
    }
    __syncthreads();
    if (t >= N_GRAPHS * 10) return;
    int g = t / 10, c = t % 10;
    float inv = 1.f / fmaxf(g_gcnt[g], 1.f);
    float s = 0.f;
#pragma unroll
    for (int o = 0; o < 32; o++) {
        float gm = g_gsum[g * 32 + o] * inv;
        float val = gm * bn[o] + bn[32 + o];
        s += val * fc[c * 32 + o];
    }
    out[g * 10 + c] = s;
}

// ---------------- launch -------------------------------------------------------
extern "C" void kernel_launch(void* const* d_in, const int* in_sizes, int n_in,
                              void* d_out, int out_size) {
    const float* x     = (const float*)d_in[0];
    const void*  ei    = d_in[1];
    const float* ea    = (const float*)d_in[2];
    const void*  batch = d_in[3];
    const float* W1    = (const float*)d_in[4];
    const float* g1    = (const float*)d_in[5];
    const float* b1    = (const float*)d_in[6];
    const float* W2    = (const float*)d_in[7];
    const float* g2    = (const float*)d_in[8];
    const float* b2    = (const float*)d_in[9];
    const float* fc    = (const float*)d_in[10];
    float* out = (float*)d_out;

    int nodeBlocks = N_NODES / 8;           // 12500, warp per node
    int edge4Blocks = N_EDGES / (256 * 4);  // 3125, 4 edges/thread

    k_count<<<edge4Blocks, 256>>>(ei);
    k_scan<<<SCAN_BLOCKS, 256>>>();
    k_scatter<<<edge4Blocks, 256>>>(ei, ea);
    k_agg1<<<nodeBlocks, 256>>>(x, W1);
    k_agg2<<<nodeBlocks, 256>>>(W2, batch, g1, b1);
    k_final<<<1, 640>>>(g2, b2, fc, out);
}

// round 15
// speedup vs baseline: 1.3470x; 1.3470x over previous
#include <cuda_runtime.h>
#include <cuda_fp16.h>
#include <math.h>

#define N_NODES 100000
#define N_EDGES 3200000
#define N_GRAPHS 64
#define SCAN_BLOCKS 391            // ceil(100000/256)

typedef unsigned long long ull;
#define C16 (1.f / 65535.f)

// ---------------- scratch -----------------------------------------------------
__device__ __align__(16) uint2 g_es[N_EDGES + 8];    // sorted by dst: {src, p1q<<16|p0q}
__device__ int   g_deg[N_NODES];
__device__ int   g_offs[N_NODES];    // exclusive offsets; scatter bumps to offs+deg
__device__ int   g_bsum[SCAN_BLOCKS + 1];
__device__ int   g_bpre[SCAN_BLOCKS + 1];
__device__ __align__(4) __half g_h1[N_NODES * 16];   // raw h1 (pre-BN), fp16
__device__ float g_stats1[32];          // sum[16], sumsq[16]
__device__ float g_stats2[64];          // sum[32], sumsq[32]
__device__ __align__(16) float g_gsum[N_GRAPHS * 32];
__device__ float g_gcnt[N_GRAPHS];
__device__ int   g_i64;

__device__ __forceinline__ float elu1(float v) { return v > 0.f ? v : expm1f(v); }

__device__ __forceinline__ int load_idx(const void* p, long long i, int f64) {
    return f64 ? (int)((const long long*)p)[i] : ((const int*)p)[i];
}

// per-warp int64-vs-int32 detection from edge_index words (warp-uniform result)
__device__ __forceinline__ int detect_i64(const int* ei, int lane) {
    int w = ei[2 * lane + 1];
    return __all_sync(0xffffffffu, w == 0) ? 1 : 0;
}

// ---------------- f32x2 packed helpers ----------------------------------------
__device__ __forceinline__ ull pkf(float lo, float hi) {
    ull r; asm("mov.b64 %0, {%1, %2};" : "=l"(r) : "f"(lo), "f"(hi)); return r;
}
__device__ __forceinline__ float2 unpk(ull v) {
    float2 f; asm("mov.b64 {%0, %1}, %2;" : "=f"(f.x), "=f"(f.y) : "l"(v)); return f;
}
__device__ __forceinline__ ull fma2(ull a, ull b, ull c) {
    ull d; asm("fma.rn.f32x2 %0, %1, %2, %3;" : "=l"(d) : "l"(a), "l"(b), "l"(c)); return d;
}
__device__ __forceinline__ ull add2(ull a, ull b) {
    ull d; asm("add.rn.f32x2 %0, %1, %2;" : "=l"(d) : "l"(a), "l"(b)); return d;
}
__device__ __forceinline__ ull sx2(ull v, int m) {
    unsigned lo = (unsigned)v, hi = (unsigned)(v >> 32);
    lo = __shfl_xor_sync(0xffffffffu, lo, m);
    hi = __shfl_xor_sync(0xffffffffu, hi, m);
    ull o; asm("mov.b64 %0, {%1, %2};" : "=l"(o) : "r"(lo), "r"(hi)); return o;
}

// ---------------- count (4 edges/thread) + detect/zero folded into block 0 -----
__global__ __launch_bounds__(256) void k_count(const void* __restrict__ ei) {
    int t = threadIdx.x, lane = t & 31;
    int f64 = detect_i64((const int*)ei, lane);
    if (blockIdx.x == 0) {
        for (int i = t; i < N_GRAPHS * 32; i += 256) g_gsum[i] = 0.f;
        if (t < 32) g_stats1[t] = 0.f;
        if (t < 64) g_stats2[t] = 0.f;
        if (t < N_GRAPHS) g_gcnt[t] = 0.f;
        if (t == 0) g_i64 = f64;
    }
    long long base = (long long)(blockIdx.x * 256 + t) * 4;
    if (base >= N_EDGES) return;
    int d0, d1, d2, d3;
    if (f64) {
        const longlong2* p = (const longlong2*)((const long long*)ei + N_EDGES + base);
        longlong2 a = p[0], b = p[1];
        d0 = (int)a.x; d1 = (int)a.y; d2 = (int)b.x; d3 = (int)b.y;
    } else {
        int4 v = *(const int4*)((const int*)ei + N_EDGES + base);
        d0 = v.x; d1 = v.y; d2 = v.z; d3 = v.w;
    }
    atomicAdd(&g_deg[d0], 1);
    atomicAdd(&g_deg[d1], 1);
    atomicAdd(&g_deg[d2], 1);
    atomicAdd(&g_deg[d3], 1);
}

// ---------------- scan stage A: per-block sums --------------------------------
__global__ __launch_bounds__(256) void k_scanA() {
    int t = threadIdx.x, lane = t & 31, warp = t >> 5;
    int i = blockIdx.x * 256 + t;
    int v = (i < N_NODES) ? g_deg[i] : 0;
#pragma unroll
    for (int s = 16; s > 0; s >>= 1) v += __shfl_xor_sync(0xffffffffu, v, s);
    __shared__ int sW[8];
    if (lane == 0) sW[warp] = v;
    __syncthreads();
    if (t == 0) {
        int s = 0;
#pragma unroll
        for (int w = 0; w < 8; w++) s += sW[w];
        g_bsum[blockIdx.x] = s;
    }
}

// ---------------- scan stage B: scan block sums -------------------------------
__global__ __launch_bounds__(512) void k_scanB() {
    int t = threadIdx.x, lane = t & 31, warp = t >> 5;
    int v = (t < SCAN_BLOCKS) ? g_bsum[t] : 0;
    int orig = v;
#pragma unroll
    for (int d = 1; d < 32; d <<= 1) {
        int u = __shfl_up_sync(0xffffffffu, v, d);
        if (lane >= d) v += u;
    }
    __shared__ int sW[16];
    if (lane == 31) sW[warp] = v;
    __syncthreads();
    if (t < 16) {
        int x = sW[t], ox = x;
#pragma unroll
        for (int d = 1; d < 16; d <<= 1) {
            int u = __shfl_up_sync(0xffffu, x, d);
            if (t >= d) x += u;
        }
        sW[t] = x - ox;
    }
    __syncthreads();
    if (t < SCAN_BLOCKS) g_bpre[t] = v - orig + sW[warp];
}

// ---------------- scan stage C: per-block exclusive scan + write --------------
__global__ __launch_bounds__(256) void k_scanC() {
    int t = threadIdx.x, lane = t & 31, warp = t >> 5;
    int i = blockIdx.x * 256 + t;
    int v = (i < N_NODES) ? g_deg[i] : 0;
    int orig = v;
#pragma unroll
    for (int d = 1; d < 32; d <<= 1) {
        int u = __shfl_up_sync(0xffffffffu, v, d);
        if (lane >= d) v += u;
    }
    __shared__ int sW[8];
    if (lane == 31) sW[warp] = v;
    __syncthreads();
    if (t < 8) {
        int x = sW[t], ox = x;
#pragma unroll
        for (int d = 1; d < 8; d <<= 1) {
            int u = __shfl_up_sync(0xffu, x, d);
            if (t >= d) x += u;
        }
        sW[t] = x - ox;
    }
    __syncthreads();
    if (i < N_NODES)
        g_offs[i] = v - orig + sW[warp] + g_bpre[blockIdx.x];
}

// ---------------- scatter: 4 edges per thread, atomics on g_offs ---------------
__global__ __launch_bounds__(256) void k_scatter(const void* __restrict__ ei,
                                                 const float* __restrict__ ea) {
    int lane = threadIdx.x & 31;
    int f64 = detect_i64((const int*)ei, lane);
    long long base = (long long)(blockIdx.x * 256 + threadIdx.x) * 4;
    if (base >= N_EDGES) return;
    int s0, s1, s2, s3, d0, d1, d2, d3;
    if (f64) {
        const longlong2* ps = (const longlong2*)((const long long*)ei + base);
        longlong2 a = ps[0], b = ps[1];
        s0 = (int)a.x; s1 = (int)a.y; s2 = (int)b.x; s3 = (int)b.y;
        const longlong2* pd = (const longlong2*)((const long long*)ei + N_EDGES + base);
        longlong2 c = pd[0], d = pd[1];
        d0 = (int)c.x; d1 = (int)c.y; d2 = (int)d.x; d3 = (int)d.y;
    } else {
        int4 vs = *(const int4*)((const int*)ei + base);
        s0 = vs.x; s1 = vs.y; s2 = vs.z; s3 = vs.w;
        int4 vd = *(const int4*)((const int*)ei + N_EDGES + base);
        d0 = vd.x; d1 = vd.y; d2 = vd.z; d3 = vd.w;
    }
    float4 ea0 = *(const float4*)(ea + 2 * base);
    float4 ea1 = *(const float4*)(ea + 2 * base + 4);
    int p0 = atomicAdd(&g_offs[d0], 1);
    int p1 = atomicAdd(&g_offs[d1], 1);
    int p2 = atomicAdd(&g_offs[d2], 1);
    int p3 = atomicAdd(&g_offs[d3], 1);
    unsigned q00 = __float2uint_rn(ea0.x * 65535.f), q01 = __float2uint_rn(ea0.y * 65535.f);
    unsigned q10 = __float2uint_rn(ea0.z * 65535.f), q11 = __float2uint_rn(ea0.w * 65535.f);
    unsigned q20 = __float2uint_rn(ea1.x * 65535.f), q21 = __float2uint_rn(ea1.y * 65535.f);
    unsigned q30 = __float2uint_rn(ea1.z * 65535.f), q31 = __float2uint_rn(ea1.w * 65535.f);
    g_es[p0] = make_uint2((unsigned)s0, (q01 << 16) | q00);
    g_es[p1] = make_uint2((unsigned)s1, (q11 << 16) | q10);
    g_es[p2] = make_uint2((unsigned)s2, (q21 << 16) | q20);
    g_es[p3] = make_uint2((unsigned)s3, (q31 << 16) | q30);
}

// ---------------- layer1: gather-aggregate + conv + ELU + BN stats ------------
// NOTE: g_offs[n] now holds offs+deg (post-scatter); base = g_offs[n] - deg.
__global__ __launch_bounds__(256) void k_agg1(const float* __restrict__ x,
                                              const float* __restrict__ W1) {
    __shared__ float sW[192];            // W1[k*48 + i*16 + o]
    __shared__ float sS[8][12];
    __shared__ float sH[8][16];
    int t = threadIdx.x;
    if (t < 192) sW[t] = W1[t];
    __syncthreads();
    int warp = t >> 5, lane = t & 31;
    int n = blockIdx.x * 8 + warp;
    int q = lane & 3, grp = lane >> 2;   // 8 edges per iter, 4 lanes/edge
    int deg = g_deg[n];
    int base = g_offs[n] - deg;
    float a0 = 0.f, a1 = 0.f, a2 = 0.f, a3 = 0.f;   // S[k][i=q]
    for (int eb = 0; eb < deg; eb += 8) {
        uint2 r = g_es[base + eb + grp];             // broadcast: 4 lanes same addr
        float act = ((eb + grp) < deg) ? 1.f : 0.f;
        float f0 = (float)(r.y & 0xffffu), f1 = (float)(r.y >> 16);
        float p0 = f0 * C16, p1 = f1 * C16;
        float q0 = fmaf(f0, -C16, 1.f), q1 = fmaf(f1, -C16, 1.f);
        float xv = 0.f;
        if (q < 3) xv = x[r.x * 3u + (unsigned)q];
        xv *= act;
        float q0q1 = q1 * q0;
        a0 += q0q1 * xv;
        a1 += (q1 * p0) * xv;
        a2 += (p1 * q0) * xv;
        a3 += (p1 * p0) * xv;
    }
#pragma unroll
    for (int s = 4; s < 32; s <<= 1) {
        a0 += __shfl_xor_sync(0xffffffffu, a0, s);
        a1 += __shfl_xor_sync(0xffffffffu, a1, s);
        a2 += __shfl_xor_sync(0xffffffffu, a2, s);
        a3 += __shfl_xor_sync(0xffffffffu, a3, s);
    }
    if (lane < 3) {
        sS[warp][0 + lane] = a0;
        sS[warp][3 + lane] = a1;
        sS[warp][6 + lane] = a2;
        sS[warp][9 + lane] = a3;
    }
    __syncwarp();
    if (lane < 16) {
        float s = 0.f;
#pragma unroll
        for (int k = 0; k < 4; k++)
#pragma unroll
            for (int i = 0; i < 3; i++)
                s += sS[warp][k * 3 + i] * sW[k * 48 + i * 16 + lane];
        float d = (float)max(deg, 1);
        float h = elu1(s / d);
        g_h1[(size_t)n * 16 + lane] = __float2half(h);
        sH[warp][lane] = h;
    }
    __syncthreads();
    if (t < 16) {
        float tot = 0.f, sq = 0.f;
#pragma unroll
        for (int w = 0; w < 8; w++) { float v = sH[w][t]; tot += v; sq += v * v; }
        atomicAdd(&g_stats1[t], tot);
        atomicAdd(&g_stats1[16 + t], sq);
    }
}

// ---------------- layer2: 8 lanes/edge, 4 edges/iter; conv+ELU+stats+pool ------
__global__ __launch_bounds__(256) void k_agg2(const float* __restrict__ W2,
                                              const void* __restrict__ batch,
                                              const float* __restrict__ gam1,
                                              const float* __restrict__ bet1) {
    __shared__ float sWt[32 * 68];        // transposed W2: [o][j], j = k*16+i
    __shared__ float sAB[32];             // A[16], B[16]
    __shared__ __align__(16) float sT[8][64];
    __shared__ float sH[8][32];
    __shared__ int   sGid[8];
    int t = threadIdx.x;
    for (int idx = t; idx < 2048; idx += 256) {
        int j = idx >> 5, o = idx & 31;
        sWt[o * 68 + j] = W2[idx];
    }
    if (t < 16) {
        float mu = g_stats1[t] * (1.f / N_NODES);
        float var = g_stats1[16 + t] * (1.f / N_NODES) - mu * mu;
        float A = rsqrtf(var + 1e-5f) * gam1[t];
        sAB[t] = A;
        sAB[16 + t] = bet1[t] - mu * A;
    }
    __syncthreads();
    int warp = t >> 5, lane = t & 31;
    int n = blockIdx.x * 8 + warp;
    int q = lane & 7, og = lane >> 3;    // 4 edges per iter, 8 lanes/edge
    int deg = g_deg[n];
    int base = g_offs[n] - deg;
    ull Sx01 = 0, Sx23 = 0, Sy01 = 0, Sy23 = 0, C01 = 0, C23 = 0;
    for (int eb = 0; eb < deg; eb += 4) {
        uint2 r = g_es[base + eb + og];              // broadcast: 8 lanes same addr
        float act = ((eb + og) < deg) ? 1.f : 0.f;
        float f0 = (float)(r.y & 0xffffu), f1 = (float)(r.y >> 16);
        float c16a = C16 * act;
        float p0a = f0 * c16a, q0a = fmaf(f0, -c16a, act);   // act folded into decode
        float p1 = f1 * C16, q1 = fmaf(f1, -C16, 1.f);
        unsigned raw = *(const unsigned*)((const char*)g_h1 + (size_t)r.x * 32 + q * 4);
        float2 hv = __half22float2(*reinterpret_cast<__half2*>(&raw));
        ull q0p0 = pkf(q0a, p0a);
        ull b01 = fma2(pkf(q1, q1), q0p0, 0ull);
        ull b23 = fma2(pkf(p1, p1), q0p0, 0ull);
        ull hx = pkf(hv.x, hv.x);
        ull hy = pkf(hv.y, hv.y);
        Sx01 = fma2(b01, hx, Sx01);
        Sx23 = fma2(b23, hx, Sx23);
        Sy01 = fma2(b01, hy, Sy01);
        Sy23 = fma2(b23, hy, Sy23);
        C01 = add2(C01, b01);
        C23 = add2(C23, b23);
    }
#pragma unroll
    for (int s = 8; s < 32; s <<= 1) {
        Sx01 = add2(Sx01, sx2(Sx01, s));
        Sx23 = add2(Sx23, sx2(Sx23, s));
        Sy01 = add2(Sy01, sx2(Sy01, s));
        Sy23 = add2(Sy23, sx2(Sy23, s));
        C01 = add2(C01, sx2(C01, s));
        C23 = add2(C23, sx2(C23, s));
    }
    if (lane < 8) {
        float2 x01 = unpk(Sx01), x23 = unpk(Sx23);
        float2 y01 = unpk(Sy01), y23 = unpk(Sy23);
        float2 c01 = unpk(C01), c23 = unpk(C23);
        int i0 = 2 * q, i1 = 2 * q + 1;
        float A0 = sAB[i0], B0 = sAB[16 + i0];
        float A1 = sAB[i1], B1 = sAB[16 + i1];
        sT[warp][0 * 16 + i0] = A0 * x01.x + B0 * c01.x;
        sT[warp][1 * 16 + i0] = A0 * x01.y + B0 * c01.y;
        sT[warp][2 * 16 + i0] = A0 * x23.x + B0 * c23.x;
        sT[warp][3 * 16 + i0] = A0 * x23.y + B0 * c23.y;
        sT[warp][0 * 16 + i1] = A1 * y01.x + B1 * c01.x;
        sT[warp][1 * 16 + i1] = A1 * y01.y + B1 * c01.y;
        sT[warp][2 * 16 + i1] = A1 * y23.x + B1 * c23.x;
        sT[warp][3 * 16 + i1] = A1 * y23.y + B1 * c23.y;
    }
    if (lane == 0) sGid[warp] = load_idx(batch, n, g_i64);
    __syncwarp();
    float s = 0.f;
    const float4* wp = (const float4*)(sWt + lane * 68);
    const float4* tp = (const float4*)(sT[warp]);
#pragma unroll
    for (int jj = 0; jj < 16; jj++) {
        float4 w4 = wp[jj], t4 = tp[jj];
        s += t4.x * w4.x + t4.y * w4.y + t4.z * w4.z + t4.w * w4.w;
    }
    float d = (float)max(deg, 1);
    float h = elu1(s / d);
    sH[warp][lane] = h;
    __syncthreads();
    if (t < 32) {
        float tot = 0.f, sq = 0.f;
#pragma unroll
        for (int w = 0; w < 8; w++) { float v = sH[w][t]; tot += v; sq += v * v; }
        atomicAdd(&g_stats2[t], tot);
        atomicAdd(&g_stats2[32 + t], sq);
        int g0 = sGid[0];
        bool uni = true;
#pragma unroll
        for (int w = 1; w < 8; w++) uni &= (sGid[w] == g0);
        if (uni) {
            atomicAdd(&g_gsum[g0 * 32 + t], tot);
            if (t == 0) atomicAdd(&g_gcnt[g0], 8.f);
        } else {
#pragma unroll
            for (int w = 0; w < 8; w++) {
                atomicAdd(&g_gsum[sGid[w] * 32 + t], sH[w][t]);
                if (t == 0) atomicAdd(&g_gcnt[sGid[w]], 1.f);
            }
        }
    }
}

// ---------------- final: bn2 params + bn2(mean-pool) @ fc^T --------------------
__global__ __launch_bounds__(640) void k_final(const float* __restrict__ gam,
                                               const float* __restrict__ bet,
                                               const float* __restrict__ fc,
                                               float* __restrict__ out) {
    __shared__ float bn[64];
    int t = threadIdx.x;
    if (t < 32) {
        float mu = g_stats2[t] * (1.f / N_NODES);
        float var = g_stats2[32 + t] * (1.f / N_NODES) - mu * mu;
        float A = rsqrtf(var + 1e-5f) * gam[t];
        bn[t] = A;
        bn[32 + t] = bet[t] - mu * A;
    }
    __syncthreads();
    if (t >= N_GRAPHS * 10) return;
    int g = t / 10, c = t % 10;
    float inv = 1.f / fmaxf(g_gcnt[g], 1.f);
    float s = 0.f;
#pragma unroll
    for (int o = 0; o < 32; o++) {
        float gm = g_gsum[g * 32 + o] * inv;
        float val = gm * bn[o] + bn[32 + o];
        s += val * fc[c * 32 + o];
    }
    out[g * 10 + c] = s;
}

// ---------------- launch -------------------------------------------------------
extern "C" void kernel_launch(void* const* d_in, const int* in_sizes, int n_in,
                              void* d_out, int out_size) {
    const float* x     = (const float*)d_in[0];
    const void*  ei    = d_in[1];
    const float* ea    = (const float*)d_in[2];
    const void*  batch = d_in[3];
    const float* W1    = (const float*)d_in[4];
    const float* g1    = (const float*)d_in[5];
    const float* b1    = (const float*)d_in[6];
    const float* W2    = (const float*)d_in[7];
    const float* g2    = (const float*)d_in[8];
    const float* b2    = (const float*)d_in[9];
    const float* fc    = (const float*)d_in[10];
    float* out = (float*)d_out;

    void* p;
    cudaGetSymbolAddress(&p, g_deg);
    cudaMemsetAsync(p, 0, sizeof(g_deg));

    int nodeBlocks = N_NODES / 8;           // 12500, warp per node
    int edge4Blocks = N_EDGES / (256 * 4);  // 3125, 4 edges/thread

    k_count<<<edge4Blocks, 256>>>(ei);
    k_scanA<<<SCAN_BLOCKS, 256>>>();
    k_scanB<<<1, 512>>>();
    k_scanC<<<SCAN_BLOCKS, 256>>>();
    k_scatter<<<edge4Blocks, 256>>>(ei, ea);
    k_agg1<<<nodeBlocks, 256>>>(x, W1);
    k_agg2<<<nodeBlocks, 256>>>(W2, batch, g1, b1);
    k_final<<<1, 640>>>(g2, b2, fc, out);
}

// round 16
// speedup vs baseline: 1.3533x; 1.0047x over previous
#include <cuda_runtime.h>
#include <cuda_fp16.h>
#include <math.h>

#define N_NODES 100000
#define N_EDGES 3200000
#define N_GRAPHS 64
#define SCAN_BLOCKS 391            // ceil(100000/256)

typedef unsigned long long ull;
#define C16 (1.f / 65535.f)

// ---------------- scratch -----------------------------------------------------
__device__ __align__(16) uint2 g_es[N_EDGES + 8];    // sorted by dst: {src, p1q<<16|p0q}
__device__ int   g_deg[N_NODES];
__device__ int   g_offs[N_NODES];    // exclusive offsets; scatter bumps to offs+deg
__device__ int   g_bsum[SCAN_BLOCKS + 1];
__device__ __align__(4) __half g_h1[N_NODES * 16];   // raw h1 (pre-BN), fp16
__device__ float g_stats1[32];          // sum[16], sumsq[16]
__device__ float g_stats2[64];          // sum[32], sumsq[32]
__device__ __align__(16) float g_gsum[N_GRAPHS * 32];
__device__ float g_gcnt[N_GRAPHS];
__device__ int   g_i64;

__device__ __forceinline__ float elu1(float v) { return v > 0.f ? v : expm1f(v); }

__device__ __forceinline__ int load_idx(const void* p, long long i, int f64) {
    return f64 ? (int)((const long long*)p)[i] : ((const int*)p)[i];
}

// per-warp int64-vs-int32 detection from edge_index words (warp-uniform result)
__device__ __forceinline__ int detect_i64(const int* ei, int lane) {
    int w = ei[2 * lane + 1];
    return __all_sync(0xffffffffu, w == 0) ? 1 : 0;
}

// ---------------- f32x2 packed helpers ----------------------------------------
__device__ __forceinline__ ull pkf(float lo, float hi) {
    ull r; asm("mov.b64 %0, {%1, %2};" : "=l"(r) : "f"(lo), "f"(hi)); return r;
}
__device__ __forceinline__ float2 unpk(ull v) {
    float2 f; asm("mov.b64 {%0, %1}, %2;" : "=f"(f.x), "=f"(f.y) : "l"(v)); return f;
}
__device__ __forceinline__ ull fma2(ull a, ull b, ull c) {
    ull d; asm("fma.rn.f32x2 %0, %1, %2, %3;" : "=l"(d) : "l"(a), "l"(b), "l"(c)); return d;
}
__device__ __forceinline__ ull add2(ull a, ull b) {
    ull d; asm("add.rn.f32x2 %0, %1, %2;" : "=l"(d) : "l"(a), "l"(b)); return d;
}
__device__ __forceinline__ ull sx2(ull v, int m) {
    unsigned lo = (unsigned)v, hi = (unsigned)(v >> 32);
    lo = __shfl_xor_sync(0xffffffffu, lo, m);
    hi = __shfl_xor_sync(0xffffffffu, hi, m);
    ull o; asm("mov.b64 %0, {%1, %2};" : "=l"(o) : "r"(lo), "r"(hi)); return o;
}

// ---------------- count (4 edges/thread) + detect/zero folded into block 0 -----
__global__ __launch_bounds__(256) void k_count(const void* __restrict__ ei) {
    int t = threadIdx.x, lane = t & 31;
    int f64 = detect_i64((const int*)ei, lane);
    if (blockIdx.x == 0) {
        for (int i = t; i < N_GRAPHS * 32; i += 256) g_gsum[i] = 0.f;
        if (t < 32) g_stats1[t] = 0.f;
        if (t < 64) g_stats2[t] = 0.f;
        if (t < N_GRAPHS) g_gcnt[t] = 0.f;
        if (t == 0) g_i64 = f64;
    }
    long long base = (long long)(blockIdx.x * 256 + t) * 4;
    if (base >= N_EDGES) return;
    int d0, d1, d2, d3;
    if (f64) {
        const longlong2* p = (const longlong2*)((const long long*)ei + N_EDGES + base);
        longlong2 a = p[0], b = p[1];
        d0 = (int)a.x; d1 = (int)a.y; d2 = (int)b.x; d3 = (int)b.y;
    } else {
        int4 v = *(const int4*)((const int*)ei + N_EDGES + base);
        d0 = v.x; d1 = v.y; d2 = v.z; d3 = v.w;
    }
    atomicAdd(&g_deg[d0], 1);
    atomicAdd(&g_deg[d1], 1);
    atomicAdd(&g_deg[d2], 1);
    atomicAdd(&g_deg[d3], 1);
}

// ---------------- scan stage A: per-block sums --------------------------------
__global__ __launch_bounds__(256) void k_scanA() {
    int t = threadIdx.x, lane = t & 31, warp = t >> 5;
    int i = blockIdx.x * 256 + t;
    int v = (i < N_NODES) ? g_deg[i] : 0;
#pragma unroll
    for (int s = 16; s > 0; s >>= 1) v += __shfl_xor_sync(0xffffffffu, v, s);
    __shared__ int sW[8];
    if (lane == 0) sW[warp] = v;
    __syncthreads();
    if (t == 0) {
        int s = 0;
#pragma unroll
        for (int w = 0; w < 8; w++) s += sW[w];
        g_bsum[blockIdx.x] = s;
    }
}

// ---------------- scan stage C: local scan + inline block-prefix ---------------
// Each block computes its own prefix over g_bsum[0..b-1] (<=391 L2-resident ints,
// warp 0, coalesced) -- replaces the separate single-block scanB launch.
__global__ __launch_bounds__(256) void k_scanC() {
    int t = threadIdx.x, lane = t & 31, warp = t >> 5;
    int b = blockIdx.x;
    int i = b * 256 + t;
    int v = (i < N_NODES) ? g_deg[i] : 0;
    int orig = v;
#pragma unroll
    for (int d = 1; d < 32; d <<= 1) {
        int u = __shfl_up_sync(0xffffffffu, v, d);
        if (lane >= d) v += u;
    }
    __shared__ int sW[8];
    __shared__ int sPrefix;
    if (lane == 31) sW[warp] = v;
    __syncthreads();
    if (t < 8) {
        int x = sW[t], ox = x;
#pragma unroll
        for (int d = 1; d < 8; d <<= 1) {
            int u = __shfl_up_sync(0xffu, x, d);
            if (t >= d) x += u;
        }
        sW[t] = x - ox;
    }
    // warp 1 computes the global block-prefix concurrently
    if (warp == 1) {
        int sum = 0;
        for (int j = lane; j < b; j += 32) sum += g_bsum[j];
#pragma unroll
        for (int s = 16; s > 0; s >>= 1) sum += __shfl_xor_sync(0xffffffffu, sum, s);
        if (lane == 0) sPrefix = sum;
    }
    __syncthreads();
    if (i < N_NODES)
        g_offs[i] = v - orig + sW[warp] + sPrefix;
}

// ---------------- scatter: 4 edges per thread, atomics on g_offs ---------------
__global__ __launch_bounds__(256) void k_scatter(const void* __restrict__ ei,
                                                 const float* __restrict__ ea) {
    int lane = threadIdx.x & 31;
    int f64 = detect_i64((const int*)ei, lane);
    long long base = (long long)(blockIdx.x * 256 + threadIdx.x) * 4;
    if (base >= N_EDGES) return;
    int s0, s1, s2, s3, d0, d1, d2, d3;
    if (f64) {
        const longlong2* ps = (const longlong2*)((const long long*)ei + base);
        longlong2 a = ps[0], b = ps[1];
        s0 = (int)a.x; s1 = (int)a.y; s2 = (int)b.x; s3 = (int)b.y;
        const longlong2* pd = (const longlong2*)((const long long*)ei + N_EDGES + base);
        longlong2 c = pd[0], d = pd[1];
        d0 = (int)c.x; d1 = (int)c.y; d2 = (int)d.x; d3 = (int)d.y;
    } else {
        int4 vs = *(const int4*)((const int*)ei + base);
        s0 = vs.x; s1 = vs.y; s2 = vs.z; s3 = vs.w;
        int4 vd = *(const int4*)((const int*)ei + N_EDGES + base);
        d0 = vd.x; d1 = vd.y; d2 = vd.z; d3 = vd.w;
    }
    float4 ea0 = *(const float4*)(ea + 2 * base);
    float4 ea1 = *(const float4*)(ea + 2 * base + 4);
    int p0 = atomicAdd(&g_offs[d0], 1);
    int p1 = atomicAdd(&g_offs[d1], 1);
    int p2 = atomicAdd(&g_offs[d2], 1);
    int p3 = atomicAdd(&g_offs[d3], 1);
    unsigned q00 = __float2uint_rn(ea0.x * 65535.f), q01 = __float2uint_rn(ea0.y * 65535.f);
    unsigned q10 = __float2uint_rn(ea0.z * 65535.f), q11 = __float2uint_rn(ea0.w * 65535.f);
    unsigned q20 = __float2uint_rn(ea1.x * 65535.f), q21 = __float2uint_rn(ea1.y * 65535.f);
    unsigned q30 = __float2uint_rn(ea1.z * 65535.f), q31 = __float2uint_rn(ea1.w * 65535.f);
    g_es[p0] = make_uint2((unsigned)s0, (q01 << 16) | q00);
    g_es[p1] = make_uint2((unsigned)s1, (q11 << 16) | q10);
    g_es[p2] = make_uint2((unsigned)s2, (q21 << 16) | q20);
    g_es[p3] = make_uint2((unsigned)s3, (q31 << 16) | q30);
}

// ---------------- layer1: gather-aggregate + conv + ELU + BN stats ------------
// NOTE: g_offs[n] now holds offs+deg (post-scatter); base = g_offs[n] - deg.
__global__ __launch_bounds__(256) void k_agg1(const float* __restrict__ x,
                                              const float* __restrict__ W1) {
    __shared__ float sW[192];            // W1[k*48 + i*16 + o]
    __shared__ float sS[8][12];
    __shared__ float sH[8][16];
    int t = threadIdx.x;
    if (t < 192) sW[t] = W1[t];
    __syncthreads();
    int warp = t >> 5, lane = t & 31;
    int n = blockIdx.x * 8 + warp;
    int q = lane & 3, grp = lane >> 2;   // 8 edges per iter, 4 lanes/edge
    int deg = g_deg[n];
    int base = g_offs[n] - deg;
    float a0 = 0.f, a1 = 0.f, a2 = 0.f, a3 = 0.f;   // S[k][i=q]
    for (int eb = 0; eb < deg; eb += 8) {
        uint2 r = g_es[base + eb + grp];             // broadcast: 4 lanes same addr
        float act = ((eb + grp) < deg) ? 1.f : 0.f;
        float f0 = (float)(r.y & 0xffffu), f1 = (float)(r.y >> 16);
        float p0 = f0 * C16, p1 = f1 * C16;
        float q0 = fmaf(f0, -C16, 1.f), q1 = fmaf(f1, -C16, 1.f);
        float xv = 0.f;
        if (q < 3) xv = x[r.x * 3u + (unsigned)q];
        xv *= act;
        float q0q1 = q1 * q0;
        a0 += q0q1 * xv;
        a1 += (q1 * p0) * xv;
        a2 += (p1 * q0) * xv;
        a3 += (p1 * p0) * xv;
    }
#pragma unroll
    for (int s = 4; s < 32; s <<= 1) {
        a0 += __shfl_xor_sync(0xffffffffu, a0, s);
        a1 += __shfl_xor_sync(0xffffffffu, a1, s);
        a2 += __shfl_xor_sync(0xffffffffu, a2, s);
        a3 += __shfl_xor_sync(0xffffffffu, a3, s);
    }
    if (lane < 3) {
        sS[warp][0 + lane] = a0;
        sS[warp][3 + lane] = a1;
        sS[warp][6 + lane] = a2;
        sS[warp][9 + lane] = a3;
    }
    __syncwarp();
    if (lane < 16) {
        float s = 0.f;
#pragma unroll
        for (int k = 0; k < 4; k++)
#pragma unroll
            for (int i = 0; i < 3; i++)
                s += sS[warp][k * 3 + i] * sW[k * 48 + i * 16 + lane];
        float d = (float)max(deg, 1);
        float h = elu1(s / d);
        g_h1[(size_t)n * 16 + lane] = __float2half(h);
        sH[warp][lane] = h;
    }
    __syncthreads();
    if (t < 16) {
        float tot = 0.f, sq = 0.f;
#pragma unroll
        for (int w = 0; w < 8; w++) { float v = sH[w][t]; tot += v; sq += v * v; }
        atomicAdd(&g_stats1[t], tot);
        atomicAdd(&g_stats1[16 + t], sq);
    }
}

// ---------------- layer2: 8 lanes/edge, 4 edges/iter; conv+ELU+stats+pool ------
__global__ __launch_bounds__(256) void k_agg2(const float* __restrict__ W2,
                                              const void* __restrict__ batch,
                                              const float* __restrict__ gam1,
                                              const float* __restrict__ bet1) {
    __shared__ float sWt[32 * 68];        // transposed W2: [o][j], j = k*16+i
    __shared__ float sAB[32];             // A[16], B[16]
    __shared__ __align__(16) float sT[8][64];
    __shared__ float sH[8][32];
    __shared__ int   sGid[8];
    int t = threadIdx.x;
    for (int idx = t; idx < 2048; idx += 256) {
        int j = idx >> 5, o = idx & 31;
        sWt[o * 68 + j] = W2[idx];
    }
    if (t < 16) {
        float mu = g_stats1[t] * (1.f / N_NODES);
        float var = g_stats1[16 + t] * (1.f / N_NODES) - mu * mu;
        float A = rsqrtf(var + 1e-5f) * gam1[t];
        sAB[t] = A;
        sAB[16 + t] = bet1[t] - mu * A;
    }
    __syncthreads();
    int warp = t >> 5, lane = t & 31;
    int n = blockIdx.x * 8 + warp;
    int q = lane & 7, og = lane >> 3;    // 4 edges per iter, 8 lanes/edge
    int deg = g_deg[n];
    int base = g_offs[n] - deg;
    ull Sx01 = 0, Sx23 = 0, Sy01 = 0, Sy23 = 0, C01 = 0, C23 = 0;
    for (int eb = 0; eb < deg; eb += 4) {
        uint2 r = g_es[base + eb + og];              // broadcast: 8 lanes same addr
        float act = ((eb + og) < deg) ? 1.f : 0.f;
        float f0 = (float)(r.y & 0xffffu), f1 = (float)(r.y >> 16);
        float c16a = C16 * act;
        float p0a = f0 * c16a, q0a = fmaf(f0, -c16a, act);   // act folded into decode
        float p1 = f1 * C16, q1 = fmaf(f1, -C16, 1.f);
        unsigned raw = *(const unsigned*)((const char*)g_h1 + (size_t)r.x * 32 + q * 4);
        float2 hv = __half22float2(*reinterpret_cast<__half2*>(&raw));
        ull q0p0 = pkf(q0a, p0a);
        ull b01 = fma2(pkf(q1, q1), q0p0, 0ull);
        ull b23 = fma2(pkf(p1, p1), q0p0, 0ull);
        ull hx = pkf(hv.x, hv.x);
        ull hy = pkf(hv.y, hv.y);
        Sx01 = fma2(b01, hx, Sx01);
        Sx23 = fma2(b23, hx, Sx23);
        Sy01 = fma2(b01, hy, Sy01);
        Sy23 = fma2(b23, hy, Sy23);
        C01 = add2(C01, b01);
        C23 = add2(C23, b23);
    }
#pragma unroll
    for (int s = 8; s < 32; s <<= 1) {
        Sx01 = add2(Sx01, sx2(Sx01, s));
        Sx23 = add2(Sx23, sx2(Sx23, s));
        Sy01 = add2(Sy01, sx2(Sy01, s));
        Sy23 = add2(Sy23, sx2(Sy23, s));
        C01 = add2(C01, sx2(C01, s));
        C23 = add2(C23, sx2(C23, s));
    }
    if (lane < 8) {
        float2 x01 = unpk(Sx01), x23 = unpk(Sx23);
        float2 y01 = unpk(Sy01), y23 = unpk(Sy23);
        float2 c01 = unpk(C01), c23 = unpk(C23);
        int i0 = 2 * q, i1 = 2 * q + 1;
        float A0 = sAB[i0], B0 = sAB[16 + i0];
        float A1 = sAB[i1], B1 = sAB[16 + i1];
        sT[warp][0 * 16 + i0] = A0 * x01.x + B0 * c01.x;
        sT[warp][1 * 16 + i0] = A0 * x01.y + B0 * c01.y;
        sT[warp][2 * 16 + i0] = A0 * x23.x + B0 * c23.x;
        sT[warp][3 * 16 + i0] = A0 * x23.y + B0 * c23.y;
        sT[warp][0 * 16 + i1] = A1 * y01.x + B1 * c01.x;
        sT[warp][1 * 16 + i1] = A1 * y01.y + B1 * c01.y;
        sT[warp][2 * 16 + i1] = A1 * y23.x + B1 * c23.x;
        sT[warp][3 * 16 + i1] = A1 * y23.y + B1 * c23.y;
    }
    if (lane == 0) sGid[warp] = load_idx(batch, n, g_i64);
    __syncwarp();
    float s = 0.f;
    const float4* wp = (const float4*)(sWt + lane * 68);
    const float4* tp = (const float4*)(sT[warp]);
#pragma unroll
    for (int jj = 0; jj < 16; jj++) {
        float4 w4 = wp[jj], t4 = tp[jj];
        s += t4.x * w4.x + t4.y * w4.y + t4.z * w4.z + t4.w * w4.w;
    }
    float d = (float)max(deg, 1);
    float h = elu1(s / d);
    sH[warp][lane] = h;
    __syncthreads();
    if (t < 32) {
        float tot = 0.f, sq = 0.f;
#pragma unroll
        for (int w = 0; w < 8; w++) { float v = sH[w][t]; tot += v; sq += v * v; }
        atomicAdd(&g_stats2[t], tot);
        atomicAdd(&g_stats2[32 + t], sq);
        int g0 = sGid[0];
        bool uni = true;
#pragma unroll
        for (int w = 1; w < 8; w++) uni &= (sGid[w] == g0);
        if (uni) {
            atomicAdd(&g_gsum[g0 * 32 + t], tot);
            if (t == 0) atomicAdd(&g_gcnt[g0], 8.f);
        } else {
#pragma unroll
            for (int w = 0; w < 8; w++) {
                atomicAdd(&g_gsum[sGid[w] * 32 + t], sH[w][t]);
                if (t == 0) atomicAdd(&g_gcnt[sGid[w]], 1.f);
            }
        }
    }
}

// ---------------- final: bn2 params + bn2(mean-pool) @ fc^T --------------------
__global__ __launch_bounds__(640) void k_final(const float* __restrict__ gam,
                                               const float* __restrict__ bet,
                                               const float* __restrict__ fc,
                                               float* __restrict__ out) {
    __shared__ float bn[64];
    int t = threadIdx.x;
    if (t < 32) {
        float mu = g_stats2[t] * (1.f / N_NODES);
        float var = g_stats2[32 + t] * (1.f / N_NODES) - mu * mu;
        float A = rsqrtf(var + 1e-5f) * gam[t];
        bn[t] = A;
        bn[32 + t] = bet[t] - mu * A;
    }
    __syncthreads();
    if (t >= N_GRAPHS * 10) return;
    int g = t / 10, c = t % 10;
    float inv = 1.f / fmaxf(g_gcnt[g], 1.f);
    float s = 0.f;
#pragma unroll
    for (int o = 0; o < 32; o++) {
        float gm = g_gsum[g * 32 + o] * inv;
        float val = gm * bn[o] + bn[32 + o];
        s += val * fc[c * 32 + o];
    }
    out[g * 10 + c] = s;
}

// ---------------- launch -------------------------------------------------------
extern "C" void kernel_launch(void* const* d_in, const int* in_sizes, int n_in,
                              void* d_out, int out_size) {
    const float* x     = (const float*)d_in[0];
    const void*  ei    = d_in[1];
    const float* ea    = (const float*)d_in[2];
    const void*  batch = d_in[3];
    const float* W1    = (const float*)d_in[4];
    const float* g1    = (const float*)d_in[5];
    const float* b1    = (const float*)d_in[6];
    const float* W2    = (const float*)d_in[7];
    const float* g2    = (const float*)d_in[8];
    const float* b2    = (const float*)d_in[9];
    const float* fc    = (const float*)d_in[10];
    float* out = (float*)d_out;

    void* p;
    cudaGetSymbolAddress(&p, g_deg);
    cudaMemsetAsync(p, 0, sizeof(g_deg));

    int nodeBlocks = N_NODES / 8;           // 12500, warp per node
    int edge4Blocks = N_EDGES / (256 * 4);  // 3125, 4 edges/thread

    k_count<<<edge4Blocks, 256>>>(ei);
    k_scanA<<<SCAN_BLOCKS, 256>>>();
    k_scanC<<<SCAN_BLOCKS, 256>>>();
    k_scatter<<<edge4Blocks, 256>>>(ei, ea);
    k_agg1<<<nodeBlocks, 256>>>(x, W1);
    k_agg2<<<nodeBlocks, 256>>>(W2, batch, g1, b1);
    k_final<<<1, 640>>>(g2, b2, fc, out);
}

// round 17
// speedup vs baseline: 1.3831x; 1.0220x over previous
#include <cuda_runtime.h>
#include <cuda_fp16.h>
#include <math.h>

#define N_NODES 100000
#define N_EDGES 3200000
#define N_GRAPHS 64
#define SCAN_BLOCKS 391            // ceil(100000/256)

typedef unsigned long long ull;
#define C16 (1.f / 65535.f)

// ---------------- scratch -----------------------------------------------------
__device__ __align__(16) uint2 g_es[N_EDGES + 8];    // sorted by dst: {src, p1q<<16|p0q}
__device__ __align__(16) int g_rank[N_EDGES];        // rank of edge within its dst bucket
__device__ int   g_deg[N_NODES];
__device__ int   g_offs[N_NODES];    // exclusive offsets (never modified after scan)
__device__ int   g_bsum[SCAN_BLOCKS + 1];
__device__ __align__(4) __half g_h1[N_NODES * 16];   // raw h1 (pre-BN), fp16
__device__ float g_stats1[32];          // sum[16], sumsq[16]
__device__ float g_stats2[64];          // sum[32], sumsq[32]
__device__ __align__(16) float g_gsum[N_GRAPHS * 32];
__device__ float g_gcnt[N_GRAPHS];
__device__ int   g_i64;

__device__ __forceinline__ float elu1(float v) { return v > 0.f ? v : expm1f(v); }

__device__ __forceinline__ int load_idx(const void* p, long long i, int f64) {
    return f64 ? (int)((const long long*)p)[i] : ((const int*)p)[i];
}

// per-warp int64-vs-int32 detection from edge_index words (warp-uniform result)
__device__ __forceinline__ int detect_i64(const int* ei, int lane) {
    int w = ei[2 * lane + 1];
    return __all_sync(0xffffffffu, w == 0) ? 1 : 0;
}

// ---------------- f32x2 packed helpers ----------------------------------------
__device__ __forceinline__ ull pkf(float lo, float hi) {
    ull r; asm("mov.b64 %0, {%1, %2};" : "=l"(r) : "f"(lo), "f"(hi)); return r;
}
__device__ __forceinline__ float2 unpk(ull v) {
    float2 f; asm("mov.b64 {%0, %1}, %2;" : "=f"(f.x), "=f"(f.y) : "l"(v)); return f;
}
__device__ __forceinline__ ull fma2(ull a, ull b, ull c) {
    ull d; asm("fma.rn.f32x2 %0, %1, %2, %3;" : "=l"(d) : "l"(a), "l"(b), "l"(c)); return d;
}
__device__ __forceinline__ ull add2(ull a, ull b) {
    ull d; asm("add.rn.f32x2 %0, %1, %2;" : "=l"(d) : "l"(a), "l"(b)); return d;
}
__device__ __forceinline__ ull sx2(ull v, int m) {
    unsigned lo = (unsigned)v, hi = (unsigned)(v >> 32);
    lo = __shfl_xor_sync(0xffffffffu, lo, m);
    hi = __shfl_xor_sync(0xffffffffu, hi, m);
    ull o; asm("mov.b64 %0, {%1, %2};" : "=l"(o) : "r"(lo), "r"(hi)); return o;
}

// ---------------- count (4 edges/thread) + rank capture + detect/zero ----------
__global__ __launch_bounds__(256) void k_count(const void* __restrict__ ei) {
    int t = threadIdx.x, lane = t & 31;
    int f64 = detect_i64((const int*)ei, lane);
    if (blockIdx.x == 0) {
        for (int i = t; i < N_GRAPHS * 32; i += 256) g_gsum[i] = 0.f;
        if (t < 32) g_stats1[t] = 0.f;
        if (t < 64) g_stats2[t] = 0.f;
        if (t < N_GRAPHS) g_gcnt[t] = 0.f;
        if (t == 0) g_i64 = f64;
    }
    long long base = (long long)(blockIdx.x * 256 + t) * 4;
    if (base >= N_EDGES) return;
    int d0, d1, d2, d3;
    if (f64) {
        const longlong2* p = (const longlong2*)((const long long*)ei + N_EDGES + base);
        longlong2 a = p[0], b = p[1];
        d0 = (int)a.x; d1 = (int)a.y; d2 = (int)b.x; d3 = (int)b.y;
    } else {
        int4 v = *(const int4*)((const int*)ei + N_EDGES + base);
        d0 = v.x; d1 = v.y; d2 = v.z; d3 = v.w;
    }
    int4 rk;
    rk.x = atomicAdd(&g_deg[d0], 1);
    rk.y = atomicAdd(&g_deg[d1], 1);
    rk.z = atomicAdd(&g_deg[d2], 1);
    rk.w = atomicAdd(&g_deg[d3], 1);
    *(int4*)(g_rank + base) = rk;      // coalesced
}

// ---------------- scan stage A: per-block sums --------------------------------
__global__ __launch_bounds__(256) void k_scanA() {
    int t = threadIdx.x, lane = t & 31, warp = t >> 5;
    int i = blockIdx.x * 256 + t;
    int v = (i < N_NODES) ? g_deg[i] : 0;
#pragma unroll
    for (int s = 16; s > 0; s >>= 1) v += __shfl_xor_sync(0xffffffffu, v, s);
    __shared__ int sW[8];
    if (lane == 0) sW[warp] = v;
    __syncthreads();
    if (t == 0) {
        int s = 0;
#pragma unroll
        for (int w = 0; w < 8; w++) s += sW[w];
        g_bsum[blockIdx.x] = s;
    }
}

// ---------------- scan stage C: local scan + inline block-prefix ---------------
__global__ __launch_bounds__(256) void k_scanC() {
    int t = threadIdx.x, lane = t & 31, warp = t >> 5;
    int b = blockIdx.x;
    int i = b * 256 + t;
    int v = (i < N_NODES) ? g_deg[i] : 0;
    int orig = v;
#pragma unroll
    for (int d = 1; d < 32; d <<= 1) {
        int u = __shfl_up_sync(0xffffffffu, v, d);
        if (lane >= d) v += u;
    }
    __shared__ int sW[8];
    __shared__ int sPrefix;
    if (lane == 31) sW[warp] = v;
    __syncthreads();
    if (t < 8) {
        int x = sW[t], ox = x;
#pragma unroll
        for (int d = 1; d < 8; d <<= 1) {
            int u = __shfl_up_sync(0xffu, x, d);
            if (t >= d) x += u;
        }
        sW[t] = x - ox;
    }
    if (warp == 1) {
        int sum = 0;
        for (int j = lane; j < b; j += 32) sum += g_bsum[j];
#pragma unroll
        for (int s = 16; s > 0; s >>= 1) sum += __shfl_xor_sync(0xffffffffu, sum, s);
        if (lane == 0) sPrefix = sum;
    }
    __syncthreads();
    if (i < N_NODES)
        g_offs[i] = v - orig + sW[warp] + sPrefix;
}

// ---------------- scatter: 4 edges per thread, NO atomics (rank-based) ---------
__global__ __launch_bounds__(256) void k_scatter(const void* __restrict__ ei,
                                                 const float* __restrict__ ea) {
    int lane = threadIdx.x & 31;
    int f64 = detect_i64((const int*)ei, lane);
    long long base = (long long)(blockIdx.x * 256 + threadIdx.x) * 4;
    if (base >= N_EDGES) return;
    int s0, s1, s2, s3, d0, d1, d2, d3;
    if (f64) {
        const longlong2* ps = (const longlong2*)((const long long*)ei + base);
        longlong2 a = ps[0], b = ps[1];
        s0 = (int)a.x; s1 = (int)a.y; s2 = (int)b.x; s3 = (int)b.y;
        const longlong2* pd = (const longlong2*)((const long long*)ei + N_EDGES + base);
        longlong2 c = pd[0], d = pd[1];
        d0 = (int)c.x; d1 = (int)c.y; d2 = (int)d.x; d3 = (int)d.y;
    } else {
        int4 vs = *(const int4*)((const int*)ei + base);
        s0 = vs.x; s1 = vs.y; s2 = vs.z; s3 = vs.w;
        int4 vd = *(const int4*)((const int*)ei + N_EDGES + base);
        d0 = vd.x; d1 = vd.y; d2 = vd.z; d3 = vd.w;
    }
    int4 rk = *(const int4*)(g_rank + base);          // coalesced
    int p0 = __ldg(&g_offs[d0]) + rk.x;               // L2-resident gather, no RMW
    int p1 = __ldg(&g_offs[d1]) + rk.y;
    int p2 = __ldg(&g_offs[d2]) + rk.z;
    int p3 = __ldg(&g_offs[d3]) + rk.w;
    float4 ea0 = *(const float4*)(ea + 2 * base);
    float4 ea1 = *(const float4*)(ea + 2 * base + 4);
    unsigned q00 = __float2uint_rn(ea0.x * 65535.f), q01 = __float2uint_rn(ea0.y * 65535.f);
    unsigned q10 = __float2uint_rn(ea0.z * 65535.f), q11 = __float2uint_rn(ea0.w * 65535.f);
    unsigned q20 = __float2uint_rn(ea1.x * 65535.f), q21 = __float2uint_rn(ea1.y * 65535.f);
    unsigned q30 = __float2uint_rn(ea1.z * 65535.f), q31 = __float2uint_rn(ea1.w * 65535.f);
    g_es[p0] = make_uint2((unsigned)s0, (q01 << 16) | q00);
    g_es[p1] = make_uint2((unsigned)s1, (q11 << 16) | q10);
    g_es[p2] = make_uint2((unsigned)s2, (q21 << 16) | q20);
    g_es[p3] = make_uint2((unsigned)s3, (q31 << 16) | q30);
}

// ---------------- layer1: gather-aggregate + conv + ELU + BN stats ------------
// g_offs[n] is exclusive; base = g_offs[n].
__global__ __launch_bounds__(256) void k_agg1(const float* __restrict__ x,
                                              const float* __restrict__ W1) {
    __shared__ float sW[192];            // W1[k*48 + i*16 + o]
    __shared__ float sS[8][12];
    __shared__ float sH[8][16];
    int t = threadIdx.x;
    if (t < 192) sW[t] = W1[t];
    __syncthreads();
    int warp = t >> 5, lane = t & 31;
    int n = blockIdx.x * 8 + warp;
    int q = lane & 3, grp = lane >> 2;   // 8 edges per iter, 4 lanes/edge
    int deg = g_deg[n];
    int base = g_offs[n];
    float a0 = 0.f, a1 = 0.f, a2 = 0.f, a3 = 0.f;   // S[k][i=q]
    for (int eb = 0; eb < deg; eb += 8) {
        uint2 r = g_es[base + eb + grp];             // broadcast: 4 lanes same addr
        float act = ((eb + grp) < deg) ? 1.f : 0.f;
        float f0 = (float)(r.y & 0xffffu), f1 = (float)(r.y >> 16);
        float p0 = f0 * C16, p1 = f1 * C16;
        float q0 = fmaf(f0, -C16, 1.f), q1 = fmaf(f1, -C16, 1.f);
        float xv = 0.f;
        if (q < 3) xv = x[r.x * 3u + (unsigned)q];
        xv *= act;
        float q0q1 = q1 * q0;
        a0 += q0q1 * xv;
        a1 += (q1 * p0) * xv;
        a2 += (p1 * q0) * xv;
        a3 += (p1 * p0) * xv;
    }
#pragma unroll
    for (int s = 4; s < 32; s <<= 1) {
        a0 += __shfl_xor_sync(0xffffffffu, a0, s);
        a1 += __shfl_xor_sync(0xffffffffu, a1, s);
        a2 += __shfl_xor_sync(0xffffffffu, a2, s);
        a3 += __shfl_xor_sync(0xffffffffu, a3, s);
    }
    if (lane < 3) {
        sS[warp][0 + lane] = a0;
        sS[warp][3 + lane] = a1;
        sS[warp][6 + lane] = a2;
        sS[warp][9 + lane] = a3;
    }
    __syncwarp();
    if (lane < 16) {
        float s = 0.f;
#pragma unroll
        for (int k = 0; k < 4; k++)
#pragma unroll
            for (int i = 0; i < 3; i++)
                s += sS[warp][k * 3 + i] * sW[k * 48 + i * 16 + lane];
        float d = (float)max(deg, 1);
        float h = elu1(s / d);
        g_h1[(size_t)n * 16 + lane] = __float2half(h);
        sH[warp][lane] = h;
    }
    __syncthreads();
    if (t < 16) {
        float tot = 0.f, sq = 0.f;
#pragma unroll
        for (int w = 0; w < 8; w++) { float v = sH[w][t]; tot += v; sq += v * v; }
        atomicAdd(&g_stats1[t], tot);
        atomicAdd(&g_stats1[16 + t], sq);
    }
}

// ---------------- layer2: 8 lanes/edge, 4 edges/iter; conv+ELU+stats+pool ------
__global__ __launch_bounds__(256) void k_agg2(const float* __restrict__ W2,
                                              const void* __restrict__ batch,
                                              const float* __restrict__ gam1,
                                              const float* __restrict__ bet1) {
    __shared__ float sWt[32 * 68];        // transposed W2: [o][j], j = k*16+i
    __shared__ float sAB[32];             // A[16], B[16]
    __shared__ __align__(16) float sT[8][64];
    __shared__ float sH[8][32];
    __shared__ int   sGid[8];
    int t = threadIdx.x;
    for (int idx = t; idx < 2048; idx += 256) {
        int j = idx >> 5, o = idx & 31;
        sWt[o * 68 + j] = W2[idx];
    }
    if (t < 16) {
        float mu = g_stats1[t] * (1.f / N_NODES);
        float var = g_stats1[16 + t] * (1.f / N_NODES) - mu * mu;
        float A = rsqrtf(var + 1e-5f) * gam1[t];
        sAB[t] = A;
        sAB[16 + t] = bet1[t] - mu * A;
    }
    __syncthreads();
    int warp = t >> 5, lane = t & 31;
    int n = blockIdx.x * 8 + warp;
    int q = lane & 7, og = lane >> 3;    // 4 edges per iter, 8 lanes/edge
    int deg = g_deg[n];
    int base = g_offs[n];
    ull Sx01 = 0, Sx23 = 0, Sy01 = 0, Sy23 = 0, C01 = 0, C23 = 0;
    for (int eb = 0; eb < deg; eb += 4) {
        uint2 r = g_es[base + eb + og];              // broadcast: 8 lanes same addr
        float act = ((eb + og) < deg) ? 1.f : 0.f;
        float f0 = (float)(r.y & 0xffffu), f1 = (float)(r.y >> 16);
        float c16a = C16 * act;
        float p0a = f0 * c16a, q0a = fmaf(f0, -c16a, act);   // act folded into decode
        float p1 = f1 * C16, q1 = fmaf(f1, -C16, 1.f);
        unsigned raw = *(const unsigned*)((const char*)g_h1 + (size_t)r.x * 32 + q * 4);
        float2 hv = __half22float2(*reinterpret_cast<__half2*>(&raw));
        ull q0p0 = pkf(q0a, p0a);
        ull b01 = fma2(pkf(q1, q1), q0p0, 0ull);
        ull b23 = fma2(pkf(p1, p1), q0p0, 0ull);
        ull hx = pkf(hv.x, hv.x);
        ull hy = pkf(hv.y, hv.y);
        Sx01 = fma2(b01, hx, Sx01);
        Sx23 = fma2(b23, hx, Sx23);
        Sy01 = fma2(b01, hy, Sy01);
        Sy23 = fma2(b23, hy, Sy23);
        C01 = add2(C01, b01);
        C23 = add2(C23, b23);
    }
#pragma unroll
    for (int s = 8; s < 32; s <<= 1) {
        Sx01 = add2(Sx01, sx2(Sx01, s));
        Sx23 = add2(Sx23, sx2(Sx23, s));
        Sy01 = add2(Sy01, sx2(Sy01, s));
        Sy23 = add2(Sy23, sx2(Sy23, s));
        C01 = add2(C01, sx2(C01, s));
        C23 = add2(C23, sx2(C23, s));
    }
    if (lane < 8) {
        float2 x01 = unpk(Sx01), x23 = unpk(Sx23);
        float2 y01 = unpk(Sy01), y23 = unpk(Sy23);
        float2 c01 = unpk(C01), c23 = unpk(C23);
        int i0 = 2 * q, i1 = 2 * q + 1;
        float A0 = sAB[i0], B0 = sAB[16 + i0];
        float A1 = sAB[i1], B1 = sAB[16 + i1];
        sT[warp][0 * 16 + i0] = A0 * x01.x + B0 * c01.x;
        sT[warp][1 * 16 + i0] = A0 * x01.y + B0 * c01.y;
        sT[warp][2 * 16 + i0] = A0 * x23.x + B0 * c23.x;
        sT[warp][3 * 16 + i0] = A0 * x23.y + B0 * c23.y;
        sT[warp][0 * 16 + i1] = A1 * y01.x + B1 * c01.x;
        sT[warp][1 * 16 + i1] = A1 * y01.y + B1 * c01.y;
        sT[warp][2 * 16 + i1] = A1 * y23.x + B1 * c23.x;
        sT[warp][3 * 16 + i1] = A1 * y23.y + B1 * c23.y;
    }
    if (lane == 0) sGid[warp] = load_idx(batch, n, g_i64);
    __syncwarp();
    float s = 0.f;
    const float4* wp = (const float4*)(sWt + lane * 68);
    const float4* tp = (const float4*)(sT[warp]);
#pragma unroll
    for (int jj = 0; jj < 16; jj++) {
        float4 w4 = wp[jj], t4 = tp[jj];
        s += t4.x * w4.x + t4.y * w4.y + t4.z * w4.z + t4.w * w4.w;
    }
    float d = (float)max(deg, 1);
    float h = elu1(s / d);
    sH[warp][lane] = h;
    __syncthreads();
    if (t < 32) {
        float tot = 0.f, sq = 0.f;
#pragma unroll
        for (int w = 0; w < 8; w++) { float v = sH[w][t]; tot += v; sq += v * v; }
        atomicAdd(&g_stats2[t], tot);
        atomicAdd(&g_stats2[32 + t], sq);
        int g0 = sGid[0];
        bool uni = true;
#pragma unroll
        for (int w = 1; w < 8; w++) uni &= (sGid[w] == g0);
        if (uni) {
            atomicAdd(&g_gsum[g0 * 32 + t], tot);
            if (t == 0) atomicAdd(&g_gcnt[g0], 8.f);
        } else {
#pragma unroll
            for (int w = 0; w < 8; w++) {
                atomicAdd(&g_gsum[sGid[w] * 32 + t], sH[w][t]);
                if (t == 0) atomicAdd(&g_gcnt[sGid[w]], 1.f);
            }
        }
    }
}

// ---------------- final: bn2 params + bn2(mean-pool) @ fc^T --------------------
__global__ __launch_bounds__(640) void k_final(const float* __restrict__ gam,
                                               const float* __restrict__ bet,
                                               const float* __restrict__ fc,
                                               float* __restrict__ out) {
    __shared__ float bn[64];
    int t = threadIdx.x;
    if (t < 32) {
        float mu = g_stats2[t] * (1.f / N_NODES);
        float var = g_stats2[32 + t] * (1.f / N_NODES) - mu * mu;
        float A = rsqrtf(var + 1e-5f) * gam[t];
        bn[t] = A;
        bn[32 + t] = bet[t] - mu * A;
    }
    __syncthreads();
    if (t >= N_GRAPHS * 10) return;
    int g = t / 10, c = t % 10;
    float inv = 1.f / fmaxf(g_gcnt[g], 1.f);
    float s = 0.f;
#pragma unroll
    for (int o = 0; o < 32; o++) {
        float gm = g_gsum[g * 32 + o] * inv;
        float val = gm * bn[o] + bn[32 + o];
        s += val * fc[c * 32 + o];
    }
    out[g * 10 + c] = s;
}

// ---------------- launch -------------------------------------------------------
extern "C" void kernel_launch(void* const* d_in, const int* in_sizes, int n_in,
                              void* d_out, int out_size) {
    const float* x     = (const float*)d_in[0];
    const void*  ei    = d_in[1];
    const float* ea    = (const float*)d_in[2];
    const void*  batch = d_in[3];
    const float* W1    = (const float*)d_in[4];
    const float* g1    = (const float*)d_in[5];
    const float* b1    = (const float*)d_in[6];
    const float* W2    = (const float*)d_in[7];
    const float* g2    = (const float*)d_in[8];
    const float* b2    = (const float*)d_in[9];
    const float* fc    = (const float*)d_in[10];
    float* out = (float*)d_out;

    void* p;
    cudaGetSymbolAddress(&p, g_deg);
    cudaMemsetAsync(p, 0, sizeof(g_deg));

    int nodeBlocks = N_NODES / 8;           // 12500, warp per node
    int edge4Blocks = N_EDGES / (256 * 4);  // 3125, 4 edges/thread

    k_count<<<edge4Blocks, 256>>>(ei);
    k_scanA<<<SCAN_BLOCKS, 256>>>();
    k_scanC<<<SCAN_BLOCKS, 256>>>();
    k_scatter<<<edge4Blocks, 256>>>(ei, ea);
    k_agg1<<<nodeBlocks, 256>>>(x, W1);
    k_agg2<<<nodeBlocks, 256>>>(W2, batch, g1, b1);
    k_final<<<1, 640>>>(g2, b2, fc, out);
}